// round 2
// baseline (speedup 1.0000x reference)
#include <cuda_runtime.h>
#include <cstdint>

// ---------------------------------------------------------------------------
// GQA causal flash attention (prefill), tf32 mma.sync path.
// S=2048, 32 Q heads, 8 KV heads, D=128. fp32 in/out.
// Tiling: Br=128 q rows x Bc=64 kv rows, 8 warps (256 thr) per CTA.
// Grid: (16 q-tiles, 32 heads).
// ---------------------------------------------------------------------------

#define SEQ_LEN    2048
#define NUM_HEADS  32
#define NUM_KV     8
#define HEAD_DIM   128
#define QSTRIDE    (NUM_HEADS * HEAD_DIM)   // 4096 floats per q row
#define KSTRIDE    (NUM_KV * HEAD_DIM)      // 1024 floats per kv row
#define SCALE_F    0.08838834764831845f

#define BR 128
#define BC 64
#define NTHREADS 256

// Padded shared-memory leading dims (in 4B words) chosen so that the
// mma fragment load pattern (lane -> gid*LD + t4, LD%32 in {4,8}) hits
// all 32 banks:
#define LDQ 132   // 132%32=4  -> bank = gid*4+t4 (distinct for gid<8,t4<4)
#define LDK 132
#define LDV 136   // 136%32=8  -> bank = t4*8+gid (distinct)
#define LDP 68    // 68%32=4

#define SMEM_WORDS (BR*LDQ + BC*LDK + BC*LDV + BR*LDP)
#define SMEM_BYTES (SMEM_WORDS * 4)

__device__ __forceinline__ unsigned f2tf(float x) {
    unsigned u;
    asm("cvt.rna.tf32.f32 %0, %1;" : "=r"(u) : "f"(x));
    return u;
}

__device__ __forceinline__ void mma_tf32(float* c, const unsigned* a, const unsigned* b) {
    asm("mma.sync.aligned.m16n8k8.row.col.f32.tf32.tf32.f32 "
        "{%0,%1,%2,%3}, {%4,%5,%6,%7}, {%8,%9}, {%0,%1,%2,%3};"
        : "+f"(c[0]), "+f"(c[1]), "+f"(c[2]), "+f"(c[3])
        : "r"(a[0]), "r"(a[1]), "r"(a[2]), "r"(a[3]),
          "r"(b[0]), "r"(b[1]));
}

__global__ void __launch_bounds__(NTHREADS, 1)
fa_tf32_kernel(const float* __restrict__ Q,
               const float* __restrict__ K,
               const float* __restrict__ V,
               float* __restrict__ O)
{
    extern __shared__ unsigned smem[];
    unsigned* sQ = smem;                    // [BR][LDQ]
    unsigned* sK = sQ + BR * LDQ;           // [BC][LDK]
    unsigned* sV = sK + BC * LDK;           // [BC][LDV]
    unsigned* sP = sV + BC * LDV;           // [BR][LDP]

    const int iq   = blockIdx.x;            // q tile (0..15)
    const int h    = blockIdx.y;            // q head (0..31)
    const int g    = h >> 2;                // kv head
    const int tid  = threadIdx.x;
    const int w    = tid >> 5;              // warp 0..7 -> m-strip
    const int lane = tid & 31;
    const int gid  = lane >> 2;             // group id 0..7
    const int t4   = lane & 3;              // thread-in-group 0..3
    const int qrow0 = iq * BR;

    // ---- load Q tile (scaled, tf32) ----
    {
        const float* qbase = Q + (size_t)qrow0 * QSTRIDE + h * HEAD_DIM;
        #pragma unroll
        for (int it = tid; it < BR * (HEAD_DIM / 4); it += NTHREADS) {
            int r  = it >> 5;               // HEAD_DIM/4 = 32 float4 per row
            int c4 = it & 31;
            float4 v4 = reinterpret_cast<const float4*>(qbase + (size_t)r * QSTRIDE)[c4];
            unsigned* dst = sQ + r * LDQ + c4 * 4;
            dst[0] = f2tf(v4.x * SCALE_F);
            dst[1] = f2tf(v4.y * SCALE_F);
            dst[2] = f2tf(v4.z * SCALE_F);
            dst[3] = f2tf(v4.w * SCALE_F);
        }
    }

    float m0 = -1e30f, m1 = -1e30f;
    float l0 = 0.f,    l1 = 0.f;
    float o[16][4];
    #pragma unroll
    for (int nt = 0; nt < 16; ++nt)
        o[nt][0] = o[nt][1] = o[nt][2] = o[nt][3] = 0.f;

    const int jend = 2 * iq + 1;            // inclusive last kv tile (causal)

    for (int j = 0; j <= jend; ++j) {
        __syncthreads();                    // previous PV done before K/V overwrite
        // ---- load K & V tiles (tf32) ----
        {
            const float* kb = K + (size_t)(j * BC) * KSTRIDE + g * HEAD_DIM;
            const float* vb = V + (size_t)(j * BC) * KSTRIDE + g * HEAD_DIM;
            #pragma unroll
            for (int it = tid; it < BC * (HEAD_DIM / 4); it += NTHREADS) {
                int r  = it >> 5;
                int c4 = it & 31;
                float4 k4 = reinterpret_cast<const float4*>(kb + (size_t)r * KSTRIDE)[c4];
                unsigned* dk = sK + r * LDK + c4 * 4;
                dk[0] = f2tf(k4.x); dk[1] = f2tf(k4.y);
                dk[2] = f2tf(k4.z); dk[3] = f2tf(k4.w);
                float4 v4 = reinterpret_cast<const float4*>(vb + (size_t)r * KSTRIDE)[c4];
                unsigned* dv = sV + r * LDV + c4 * 4;
                dv[0] = f2tf(v4.x); dv[1] = f2tf(v4.y);
                dv[2] = f2tf(v4.z); dv[3] = f2tf(v4.w);
            }
        }
        __syncthreads();

        // ---- S = Q @ K^T (this warp: rows [w*16, w*16+16), cols [0,64)) ----
        float s[8][4];
        #pragma unroll
        for (int nt = 0; nt < 8; ++nt)
            s[nt][0] = s[nt][1] = s[nt][2] = s[nt][3] = 0.f;

        #pragma unroll
        for (int k0 = 0; k0 < HEAD_DIM; k0 += 8) {
            unsigned a[4];
            const unsigned* qb = sQ + (w * 16 + gid) * LDQ + k0;
            a[0] = qb[t4];
            a[1] = qb[8 * LDQ + t4];
            a[2] = qb[t4 + 4];
            a[3] = qb[8 * LDQ + t4 + 4];
            #pragma unroll
            for (int nt = 0; nt < 8; ++nt) {
                unsigned b[2];
                const unsigned* kb = sK + (nt * 8 + gid) * LDK + k0;
                b[0] = kb[t4];
                b[1] = kb[t4 + 4];
                mma_tf32(s[nt], a, b);
            }
        }

        // ---- causal mask (only partial tiles j >= 2*iq) ----
        if (j >= 2 * iq) {
            const int row0 = qrow0 + w * 16 + gid;
            const int row1 = row0 + 8;
            #pragma unroll
            for (int nt = 0; nt < 8; ++nt) {
                int col = j * BC + nt * 8 + 2 * t4;
                if (col     > row0) s[nt][0] = -1e30f;
                if (col + 1 > row0) s[nt][1] = -1e30f;
                if (col     > row1) s[nt][2] = -1e30f;
                if (col + 1 > row1) s[nt][3] = -1e30f;
            }
        }

        // ---- online softmax ----
        float tmax0 = -1e30f, tmax1 = -1e30f;
        #pragma unroll
        for (int nt = 0; nt < 8; ++nt) {
            tmax0 = fmaxf(tmax0, fmaxf(s[nt][0], s[nt][1]));
            tmax1 = fmaxf(tmax1, fmaxf(s[nt][2], s[nt][3]));
        }
        tmax0 = fmaxf(tmax0, __shfl_xor_sync(0xffffffffu, tmax0, 1));
        tmax0 = fmaxf(tmax0, __shfl_xor_sync(0xffffffffu, tmax0, 2));
        tmax1 = fmaxf(tmax1, __shfl_xor_sync(0xffffffffu, tmax1, 1));
        tmax1 = fmaxf(tmax1, __shfl_xor_sync(0xffffffffu, tmax1, 2));

        const float newm0 = fmaxf(m0, tmax0);
        const float newm1 = fmaxf(m1, tmax1);
        const float c0 = __expf(m0 - newm0);
        const float c1 = __expf(m1 - newm1);
        m0 = newm0; m1 = newm1;

        float rs0 = 0.f, rs1 = 0.f;
        unsigned* pr0 = sP + (w * 16 + gid) * LDP + 2 * t4;
        unsigned* pr1 = pr0 + 8 * LDP;
        #pragma unroll
        for (int nt = 0; nt < 8; ++nt) {
            float p0 = __expf(s[nt][0] - m0);
            float p1 = __expf(s[nt][1] - m0);
            float p2 = __expf(s[nt][2] - m1);
            float p3 = __expf(s[nt][3] - m1);
            rs0 += p0 + p1;
            rs1 += p2 + p3;
            pr0[nt * 8]     = f2tf(p0);
            pr0[nt * 8 + 1] = f2tf(p1);
            pr1[nt * 8]     = f2tf(p2);
            pr1[nt * 8 + 1] = f2tf(p3);
        }
        rs0 += __shfl_xor_sync(0xffffffffu, rs0, 1);
        rs0 += __shfl_xor_sync(0xffffffffu, rs0, 2);
        rs1 += __shfl_xor_sync(0xffffffffu, rs1, 1);
        rs1 += __shfl_xor_sync(0xffffffffu, rs1, 2);
        l0 = l0 * c0 + rs0;
        l1 = l1 * c1 + rs1;

        #pragma unroll
        for (int nt = 0; nt < 16; ++nt) {
            o[nt][0] *= c0; o[nt][1] *= c0;
            o[nt][2] *= c1; o[nt][3] *= c1;
        }
        __syncthreads();                    // P visible to all warps of... (per-warp P rows only read by same warp, but V reads need K/V load fence anyway; keep full sync)

        // ---- O += P @ V ----
        #pragma unroll
        for (int k0 = 0; k0 < BC; k0 += 8) {
            unsigned a[4];
            const unsigned* pb = sP + (w * 16 + gid) * LDP + k0;
            a[0] = pb[t4];
            a[1] = pb[8 * LDP + t4];
            a[2] = pb[t4 + 4];
            a[3] = pb[8 * LDP + t4 + 4];
            #pragma unroll
            for (int nt = 0; nt < 16; ++nt) {
                unsigned b[2];
                const unsigned* vb = sV + (k0 + t4) * LDV + nt * 8 + gid;
                b[0] = vb[0];
                b[1] = vb[4 * LDV];
                mma_tf32(o[nt], a, b);
            }
        }
    }

    // ---- epilogue: normalize and store ----
    const float inv0 = 1.f / l0;
    const float inv1 = 1.f / l1;
    const int r0 = qrow0 + w * 16 + gid;
    float* ob0 = O + (size_t)r0 * QSTRIDE + h * HEAD_DIM + 2 * t4;
    float* ob1 = ob0 + (size_t)8 * QSTRIDE;
    #pragma unroll
    for (int nt = 0; nt < 16; ++nt) {
        float2 v0 = make_float2(o[nt][0] * inv0, o[nt][1] * inv0);
        float2 v1 = make_float2(o[nt][2] * inv1, o[nt][3] * inv1);
        *reinterpret_cast<float2*>(ob0 + nt * 8) = v0;
        *reinterpret_cast<float2*>(ob1 + nt * 8) = v1;
    }
}

extern "C" void kernel_launch(void* const* d_in, const int* in_sizes, int n_in,
                              void* d_out, int out_size)
{
    const float* Q = (const float*)d_in[0];
    const float* K = (const float*)d_in[1];
    const float* V = (const float*)d_in[2];
    float* O = (float*)d_out;

    cudaFuncSetAttribute(fa_tf32_kernel,
                         cudaFuncAttributeMaxDynamicSharedMemorySize, SMEM_BYTES);
    dim3 grid(SEQ_LEN / BR, NUM_HEADS);
    fa_tf32_kernel<<<grid, NTHREADS, SMEM_BYTES>>>(Q, K, V, O);
}

// round 6
// speedup vs baseline: 1.0800x; 1.0800x over previous
#include <cuda_runtime.h>
#include <cstdint>

// ---------------------------------------------------------------------------
// GQA causal flash attention (prefill), tf32 mma.sync, sm_103-compatible.
// S=2048, 32 Q heads / 8 KV heads, D=128, fp32 in/out.
// Br=128 q rows x Bc=64 kv rows, 8 warps, warp m-strip = 16 rows.
// Q fragments in registers; P via quad-shuffle (no smem round trip);
// K/V double-buffered via cp.async with 1-tile prefetch; XOR swizzle.
// ---------------------------------------------------------------------------

#define NUM_HEADS 32
#define HEAD_DIM  128
#define QSTRIDE   4096
#define KSTRIDE   1024
#define BR 128
#define BC 64
#define NTHREADS 256

// smem: [K0 32KB][K1 32KB][V0 32KB][V1 32KB]  (floats: 8192 each)
#define SMEM_BYTES (4 * 32768)

static __device__ __forceinline__ uint32_t smem_u32(const void* p) {
    uint32_t a;
    asm("{ .reg .u64 t; cvta.to.shared.u64 t, %1; cvt.u32.u64 %0, t; }" : "=r"(a) : "l"(p));
    return a;
}
static __device__ __forceinline__ unsigned f2tf(float x) {
    unsigned u; asm("cvt.rna.tf32.f32 %0, %1;" : "=r"(u) : "f"(x)); return u;
}
static __device__ __forceinline__ float ex2f(float x) {
    float y; asm("ex2.approx.ftz.f32 %0, %1;" : "=f"(y) : "f"(x)); return y;
}
static __device__ __forceinline__ void mma_tf32(float* c, const unsigned* a, const unsigned* b) {
    asm("mma.sync.aligned.m16n8k8.row.col.f32.tf32.tf32.f32 "
        "{%0,%1,%2,%3}, {%4,%5,%6,%7}, {%8,%9}, {%0,%1,%2,%3};"
        : "+f"(c[0]), "+f"(c[1]), "+f"(c[2]), "+f"(c[3])
        : "r"(a[0]), "r"(a[1]), "r"(a[2]), "r"(a[3]), "r"(b[0]), "r"(b[1]));
}
static __device__ __forceinline__ void cpa16(uint32_t dst, const float* src) {
    asm volatile("cp.async.cg.shared.global [%0], [%1], 16;"
                 :: "r"(dst), "l"(__cvta_generic_to_global(src)) : "memory");
}
#define CP_COMMIT() asm volatile("cp.async.commit_group;" ::: "memory")
#define CP_WAIT1()  asm volatile("cp.async.wait_group 1;" ::: "memory")
#define CP_WAIT0()  asm volatile("cp.async.wait_group 0;" ::: "memory")

__global__ void __launch_bounds__(NTHREADS, 1)
fa_tf32_v3(const float* __restrict__ Q, const float* __restrict__ K,
           const float* __restrict__ V, float* __restrict__ O)
{
    extern __shared__ float sm[];
    const uint32_t sb = smem_u32(sm);

    const int iq   = (int)gridDim.x - 1 - (int)blockIdx.x;   // longest first
    const int h    = blockIdx.y;
    const int g    = h >> 2;
    const int tid  = threadIdx.x;
    const int w    = tid >> 5;
    const int lane = tid & 31;
    const int gid  = lane >> 2;
    const int t4   = lane & 3;
    const int qrow0  = iq * BR;
    const int row0   = qrow0 + w * 16 + gid;
    const int row1   = row0 + 8;
    const int maxrow = qrow0 + w * 16 + 15;

    // ---- stage tile 0 (cp.async prefetch), then Q fragments from gmem ----
    {
        const float* kg = K + (size_t)0 * KSTRIDE + g * HEAD_DIM;
        const float* vg = V + g * HEAD_DIM;
        #pragma unroll
        for (int t = 0; t < 8; ++t) {
            int idx = tid + t * NTHREADS;
            int r = idx >> 5, c4 = idx & 31;
            int kcol = (c4 * 4) ^ ((r & 7) << 2);
            int vcol = (c4 * 4) ^ ((r & 3) << 3);
            cpa16(sb + (uint32_t)(r * 128 + kcol) * 4,          kg + (size_t)r * KSTRIDE + c4 * 4);
            cpa16(sb + 65536u + (uint32_t)(r * 128 + vcol) * 4, vg + (size_t)r * KSTRIDE + c4 * 4);
        }
        CP_COMMIT();
    }

    unsigned aq[16][4];
    {
        const float* q0 = Q + (size_t)row0 * QSTRIDE + h * HEAD_DIM;
        const float* q1 = q0 + (size_t)8 * QSTRIDE;
        const float sc = (float)(0.08838834764831845 * 1.4426950408889634); // scale*log2(e)
        #pragma unroll
        for (int kc = 0; kc < 16; ++kc) {
            int c = kc * 8 + t4;
            aq[kc][0] = f2tf(q0[c] * sc);
            aq[kc][1] = f2tf(q1[c] * sc);
            aq[kc][2] = f2tf(q0[c + 4] * sc);
            aq[kc][3] = f2tf(q1[c + 4] * sc);
        }
    }

    float m0 = -1e30f, m1 = -1e30f, l0 = 0.f, l1 = 0.f;
    float o[16][4];
    #pragma unroll
    for (int nt = 0; nt < 16; ++nt)
        o[nt][0] = o[nt][1] = o[nt][2] = o[nt][3] = 0.f;

    const int jend = 2 * iq + 1;

    for (int j = 0; j <= jend; ++j) {
        // prefetch j+1 into the other buffer (its last readers finished at end of j-1)
        if (j < jend) {
            int b = (j + 1) & 1;
            const float* kg = K + (size_t)((j + 1) * BC) * KSTRIDE + g * HEAD_DIM;
            const float* vg = V + (size_t)((j + 1) * BC) * KSTRIDE + g * HEAD_DIM;
            uint32_t kd = sb + (uint32_t)b * 32768u;
            uint32_t vd = sb + 65536u + (uint32_t)b * 32768u;
            #pragma unroll
            for (int t = 0; t < 8; ++t) {
                int idx = tid + t * NTHREADS;
                int r = idx >> 5, c4 = idx & 31;
                int kcol = (c4 * 4) ^ ((r & 7) << 2);
                int vcol = (c4 * 4) ^ ((r & 3) << 3);
                cpa16(kd + (uint32_t)(r * 128 + kcol) * 4, kg + (size_t)r * KSTRIDE + c4 * 4);
                cpa16(vd + (uint32_t)(r * 128 + vcol) * 4, vg + (size_t)r * KSTRIDE + c4 * 4);
            }
            CP_COMMIT();
            CP_WAIT1();            // tile j complete, tile j+1 still in flight
        } else {
            CP_WAIT0();
        }
        __syncthreads();

        const float* kbuf = sm + (size_t)(j & 1) * 8192;
        const float* vbuf = sm + 16384 + (size_t)(j & 1) * 8192;

        const int d = maxrow - BC * j;
        if (d >= 0) {
            const int nlim = d >> 3 > 7 ? 7 : (d >> 3);

            // ---- GEMM1: S = Q @ K^T  (raw fp32-as-tf32 B operands) ----
            float s[8][4];
            #pragma unroll
            for (int nt = 0; nt < 8; ++nt)
                s[nt][0] = s[nt][1] = s[nt][2] = s[nt][3] = 0.f;

            #pragma unroll
            for (int kc = 0; kc < 16; ++kc) {
                const int c0 = (kc * 8 + t4) ^ (gid << 2);
                const int c1 = (kc * 8 + t4 + 4) ^ (gid << 2);
                #pragma unroll
                for (int nt = 0; nt < 8; ++nt) {
                    if (nt <= nlim) {
                        const float* kr = kbuf + (nt * 8 + gid) * 128;
                        unsigned b[2];
                        b[0] = __float_as_uint(kr[c0]);
                        b[1] = __float_as_uint(kr[c1]);
                        mma_tf32(s[nt], aq[kc], b);
                    }
                }
            }

            // ---- mask + online softmax (log2 domain) ----
            const bool diag = (j >= 2 * iq);
            float mx0 = -1e30f, mx1 = -1e30f;
            #pragma unroll
            for (int nt = 0; nt < 8; ++nt) {
                if (nt <= nlim) {
                    if (diag) {
                        int col = j * BC + nt * 8 + 2 * t4;
                        if (col     > row0) s[nt][0] = -1e30f;
                        if (col + 1 > row0) s[nt][1] = -1e30f;
                        if (col     > row1) s[nt][2] = -1e30f;
                        if (col + 1 > row1) s[nt][3] = -1e30f;
                    }
                    mx0 = fmaxf(mx0, fmaxf(s[nt][0], s[nt][1]));
                    mx1 = fmaxf(mx1, fmaxf(s[nt][2], s[nt][3]));
                }
            }
            mx0 = fmaxf(mx0, __shfl_xor_sync(0xffffffffu, mx0, 1));
            mx0 = fmaxf(mx0, __shfl_xor_sync(0xffffffffu, mx0, 2));
            mx1 = fmaxf(mx1, __shfl_xor_sync(0xffffffffu, mx1, 1));
            mx1 = fmaxf(mx1, __shfl_xor_sync(0xffffffffu, mx1, 2));

            const float nm0 = fmaxf(m0, mx0);
            const float nm1 = fmaxf(m1, mx1);
            const float cf0 = ex2f(m0 - nm0);
            const float cf1 = ex2f(m1 - nm1);
            m0 = nm0; m1 = nm1;

            float rs0 = 0.f, rs1 = 0.f;
            #pragma unroll
            for (int nt = 0; nt < 8; ++nt) {
                if (nt <= nlim) {
                    float p0 = ex2f(s[nt][0] - m0);
                    float p1 = ex2f(s[nt][1] - m0);
                    float p2 = ex2f(s[nt][2] - m1);
                    float p3 = ex2f(s[nt][3] - m1);
                    rs0 += p0 + p1; rs1 += p2 + p3;
                    s[nt][0] = p0; s[nt][1] = p1; s[nt][2] = p2; s[nt][3] = p3;
                }
            }
            rs0 += __shfl_xor_sync(0xffffffffu, rs0, 1);
            rs0 += __shfl_xor_sync(0xffffffffu, rs0, 2);
            rs1 += __shfl_xor_sync(0xffffffffu, rs1, 1);
            rs1 += __shfl_xor_sync(0xffffffffu, rs1, 2);
            l0 = l0 * cf0 + rs0;
            l1 = l1 * cf1 + rs1;

            #pragma unroll
            for (int nt = 0; nt < 16; ++nt) {
                o[nt][0] *= cf0; o[nt][1] *= cf0;
                o[nt][2] *= cf1; o[nt][3] *= cf1;
            }

            // ---- GEMM2: O += P @ V  (A via quad shuffles, B raw fp32) ----
            const int srcA = (lane & ~3) | (t4 >> 1);
            const bool odd = (t4 & 1);
            #pragma unroll
            for (int kc = 0; kc < 8; ++kc) {
                if (kc <= nlim) {
                    float v0 = __shfl_sync(0xffffffffu, s[kc][0], srcA);
                    float v1 = __shfl_sync(0xffffffffu, s[kc][1], srcA);
                    float v2 = __shfl_sync(0xffffffffu, s[kc][2], srcA);
                    float v3 = __shfl_sync(0xffffffffu, s[kc][3], srcA);
                    float u0 = __shfl_sync(0xffffffffu, s[kc][0], srcA + 2);
                    float u1 = __shfl_sync(0xffffffffu, s[kc][1], srcA + 2);
                    float u2 = __shfl_sync(0xffffffffu, s[kc][2], srcA + 2);
                    float u3 = __shfl_sync(0xffffffffu, s[kc][3], srcA + 2);
                    unsigned a[4];
                    a[0] = f2tf(odd ? v1 : v0);
                    a[1] = f2tf(odd ? v3 : v2);
                    a[2] = f2tf(odd ? u1 : u0);
                    a[3] = f2tf(odd ? u3 : u2);
                    const float* vr = vbuf + (kc * 8 + t4) * 128;
                    const int cs = t4 << 3;
                    #pragma unroll
                    for (int nt2 = 0; nt2 < 16; ++nt2) {
                        int c = (nt2 * 8 + gid) ^ cs;
                        unsigned b[2];
                        b[0] = __float_as_uint(vr[c]);
                        b[1] = __float_as_uint(vr[512 + c]);   // row +4
                        mma_tf32(o[nt2], a, b);
                    }
                }
            }
        }
        __syncthreads();
    }

    // ---- epilogue: normalize and store ----
    const float inv0 = 1.f / l0;
    const float inv1 = 1.f / l1;
    float* ob0 = O + (size_t)row0 * QSTRIDE + h * HEAD_DIM + 2 * t4;
    float* ob1 = ob0 + (size_t)8 * QSTRIDE;
    #pragma unroll
    for (int nt = 0; nt < 16; ++nt) {
        float2 x0 = make_float2(o[nt][0] * inv0, o[nt][1] * inv0);
        float2 x1 = make_float2(o[nt][2] * inv1, o[nt][3] * inv1);
        *reinterpret_cast<float2*>(ob0 + nt * 8) = x0;
        *reinterpret_cast<float2*>(ob1 + nt * 8) = x1;
    }
}

extern "C" void kernel_launch(void* const* d_in, const int* in_sizes, int n_in,
                              void* d_out, int out_size)
{
    const float* Q = (const float*)d_in[0];
    const float* K = (const float*)d_in[1];
    const float* V = (const float*)d_in[2];
    float* O = (float*)d_out;

    cudaFuncSetAttribute(fa_tf32_v3,
                         cudaFuncAttributeMaxDynamicSharedMemorySize, SMEM_BYTES);
    dim3 grid(2048 / BR, NUM_HEADS);
    fa_tf32_v3<<<grid, NTHREADS, SMEM_BYTES>>>(Q, K, V, O);
}

// round 7
// speedup vs baseline: 1.4010x; 1.2972x over previous
#include <cuda_runtime.h>
#include <cuda_fp16.h>
#include <cstdint>

// ---------------------------------------------------------------------------
// GQA causal flash attention (prefill), fp16 mma.sync m16n8k16, f32 accum.
// S=2048, 32 Q heads / 8 KV heads, D=128, fp32 in/out.
// Br=128 x Bc=64, 8 warps, warp m-strip = 16 rows.
// Q fragments (fp16) in registers; P = direct C->A fragment repack (no
// shuffles); K/V fp32 in smem via cp.async double buffer, converted to fp16
// at fragment build.
// ---------------------------------------------------------------------------

#define NUM_HEADS 32
#define HEAD_DIM  128
#define QSTRIDE   4096
#define KSTRIDE   1024
#define BR 128
#define BC 64
#define NTHREADS 256

// smem: [K0 32KB][K1 32KB][V0 32KB][V1 32KB]
#define SMEM_BYTES (4 * 32768)

static __device__ __forceinline__ uint32_t smem_u32(const void* p) {
    uint32_t a;
    asm("{ .reg .u64 t; cvta.to.shared.u64 t, %1; cvt.u32.u64 %0, t; }" : "=r"(a) : "l"(p));
    return a;
}
static __device__ __forceinline__ float ex2f(float x) {
    float y; asm("ex2.approx.ftz.f32 %0, %1;" : "=f"(y) : "f"(x)); return y;
}
static __device__ __forceinline__ unsigned packh2(float lo, float hi) {
    __half2 h = __floats2half2_rn(lo, hi);   // .x = lo (low 16 bits)
    return *reinterpret_cast<unsigned*>(&h);
}
static __device__ __forceinline__ void mma_f16(float* c, const unsigned* a, const unsigned* b) {
    asm("mma.sync.aligned.m16n8k16.row.col.f32.f16.f16.f32 "
        "{%0,%1,%2,%3}, {%4,%5,%6,%7}, {%8,%9}, {%0,%1,%2,%3};"
        : "+f"(c[0]), "+f"(c[1]), "+f"(c[2]), "+f"(c[3])
        : "r"(a[0]), "r"(a[1]), "r"(a[2]), "r"(a[3]), "r"(b[0]), "r"(b[1]));
}
static __device__ __forceinline__ void cpa16(uint32_t dst, const float* src) {
    asm volatile("cp.async.cg.shared.global [%0], [%1], 16;"
                 :: "r"(dst), "l"(__cvta_generic_to_global(src)) : "memory");
}
#define CP_COMMIT() asm volatile("cp.async.commit_group;" ::: "memory")
#define CP_WAIT1()  asm volatile("cp.async.wait_group 1;" ::: "memory")
#define CP_WAIT0()  asm volatile("cp.async.wait_group 0;" ::: "memory")

__global__ void __launch_bounds__(NTHREADS, 1)
fa_f16_v4(const float* __restrict__ Q, const float* __restrict__ K,
          const float* __restrict__ V, float* __restrict__ O)
{
    extern __shared__ float sm[];
    const uint32_t sb = smem_u32(sm);

    const int iq   = (int)gridDim.x - 1 - (int)blockIdx.x;   // longest first
    const int h    = blockIdx.y;
    const int g    = h >> 2;
    const int tid  = threadIdx.x;
    const int w    = tid >> 5;
    const int lane = tid & 31;
    const int gid  = lane >> 2;
    const int t4   = lane & 3;
    const int qrow0  = iq * BR;
    const int row0   = qrow0 + w * 16 + gid;
    const int row1   = row0 + 8;
    const int maxrow = qrow0 + w * 16 + 15;

    // ---- stage tile 0 (cp.async): K swizzle (r&7)<<3, V swizzle ((r>>1)&3)<<3 ----
    {
        const float* kg = K + g * HEAD_DIM;
        const float* vg = V + g * HEAD_DIM;
        #pragma unroll
        for (int t = 0; t < 8; ++t) {
            int idx = tid + t * NTHREADS;
            int r = idx >> 5, c4 = idx & 31;
            int kcol = (c4 * 4) ^ ((r & 7) << 3);
            int vcol = (c4 * 4) ^ (((r >> 1) & 3) << 3);
            cpa16(sb + (uint32_t)(r * 128 + kcol) * 4,          kg + (size_t)r * KSTRIDE + c4 * 4);
            cpa16(sb + 65536u + (uint32_t)(r * 128 + vcol) * 4, vg + (size_t)r * KSTRIDE + c4 * 4);
        }
        CP_COMMIT();
    }

    // ---- Q fragments (fp16, pre-scaled by softmax_scale * log2(e)) ----
    unsigned aq[8][4];
    {
        const float* q0 = Q + (size_t)row0 * QSTRIDE + h * HEAD_DIM;
        const float* q1 = q0 + (size_t)8 * QSTRIDE;
        const float sc = (float)(0.08838834764831845 * 1.4426950408889634);
        #pragma unroll
        for (int kc = 0; kc < 8; ++kc) {
            int c = kc * 16 + 2 * t4;
            aq[kc][0] = packh2(q0[c] * sc,     q0[c + 1] * sc);
            aq[kc][1] = packh2(q1[c] * sc,     q1[c + 1] * sc);
            aq[kc][2] = packh2(q0[c + 8] * sc, q0[c + 9] * sc);
            aq[kc][3] = packh2(q1[c + 8] * sc, q1[c + 9] * sc);
        }
    }

    float m0 = -1e30f, m1 = -1e30f, l0 = 0.f, l1 = 0.f;
    float o[16][4];
    #pragma unroll
    for (int nt = 0; nt < 16; ++nt)
        o[nt][0] = o[nt][1] = o[nt][2] = o[nt][3] = 0.f;

    const int jend = 2 * iq + 1;

    for (int j = 0; j <= jend; ++j) {
        if (j < jend) {
            int b = (j + 1) & 1;
            const float* kg = K + (size_t)((j + 1) * BC) * KSTRIDE + g * HEAD_DIM;
            const float* vg = V + (size_t)((j + 1) * BC) * KSTRIDE + g * HEAD_DIM;
            uint32_t kd = sb + (uint32_t)b * 32768u;
            uint32_t vd = sb + 65536u + (uint32_t)b * 32768u;
            #pragma unroll
            for (int t = 0; t < 8; ++t) {
                int idx = tid + t * NTHREADS;
                int r = idx >> 5, c4 = idx & 31;
                int kcol = (c4 * 4) ^ ((r & 7) << 3);
                int vcol = (c4 * 4) ^ (((r >> 1) & 3) << 3);
                cpa16(kd + (uint32_t)(r * 128 + kcol) * 4, kg + (size_t)r * KSTRIDE + c4 * 4);
                cpa16(vd + (uint32_t)(r * 128 + vcol) * 4, vg + (size_t)r * KSTRIDE + c4 * 4);
            }
            CP_COMMIT();
            CP_WAIT1();
        } else {
            CP_WAIT0();
        }
        __syncthreads();

        const float* kbuf = sm + (size_t)(j & 1) * 8192;
        const float* vbuf = sm + 16384 + (size_t)(j & 1) * 8192;

        const int d = maxrow - BC * j;
        if (d >= 0) {
            const int nlim = (d >> 3) > 7 ? 7 : (d >> 3);

            // ---- GEMM1: S = Q @ K^T (fp16 fragments built from fp32 smem) ----
            float s[8][4];
            #pragma unroll
            for (int nt = 0; nt < 8; ++nt)
                s[nt][0] = s[nt][1] = s[nt][2] = s[nt][3] = 0.f;

            #pragma unroll
            for (int kc = 0; kc < 8; ++kc) {
                const int k0 = kc * 16 + 2 * t4;
                #pragma unroll
                for (int nt = 0; nt < 8; ++nt) {
                    if (nt <= nlim) {
                        const float* kr = kbuf + (nt * 8 + gid) * 128;
                        const int sw = gid << 3;
                        float2 f0 = *reinterpret_cast<const float2*>(kr + (k0 ^ sw));
                        float2 f1 = *reinterpret_cast<const float2*>(kr + ((k0 + 8) ^ sw));
                        unsigned b[2];
                        b[0] = packh2(f0.x, f0.y);
                        b[1] = packh2(f1.x, f1.y);
                        mma_f16(s[nt], aq[kc], b);
                    }
                }
            }

            // ---- mask + online softmax (log2 domain) ----
            const bool diag = (j >= 2 * iq);
            float mx0 = -1e30f, mx1 = -1e30f;
            #pragma unroll
            for (int nt = 0; nt < 8; ++nt) {
                if (nt <= nlim) {
                    if (diag) {
                        int col = j * BC + nt * 8 + 2 * t4;
                        if (col     > row0) s[nt][0] = -1e30f;
                        if (col + 1 > row0) s[nt][1] = -1e30f;
                        if (col     > row1) s[nt][2] = -1e30f;
                        if (col + 1 > row1) s[nt][3] = -1e30f;
                    }
                    mx0 = fmaxf(mx0, fmaxf(s[nt][0], s[nt][1]));
                    mx1 = fmaxf(mx1, fmaxf(s[nt][2], s[nt][3]));
                }
            }
            mx0 = fmaxf(mx0, __shfl_xor_sync(0xffffffffu, mx0, 1));
            mx0 = fmaxf(mx0, __shfl_xor_sync(0xffffffffu, mx0, 2));
            mx1 = fmaxf(mx1, __shfl_xor_sync(0xffffffffu, mx1, 1));
            mx1 = fmaxf(mx1, __shfl_xor_sync(0xffffffffu, mx1, 2));

            const float nm0 = fmaxf(m0, mx0);
            const float nm1 = fmaxf(m1, mx1);
            const float cf0 = ex2f(m0 - nm0);
            const float cf1 = ex2f(m1 - nm1);
            m0 = nm0; m1 = nm1;

            float rs0 = 0.f, rs1 = 0.f;
            #pragma unroll
            for (int nt = 0; nt < 8; ++nt) {
                if (nt <= nlim) {
                    float p0 = ex2f(s[nt][0] - m0);
                    float p1 = ex2f(s[nt][1] - m0);
                    float p2 = ex2f(s[nt][2] - m1);
                    float p3 = ex2f(s[nt][3] - m1);
                    rs0 += p0 + p1; rs1 += p2 + p3;
                    s[nt][0] = p0; s[nt][1] = p1; s[nt][2] = p2; s[nt][3] = p3;
                }
            }
            rs0 += __shfl_xor_sync(0xffffffffu, rs0, 1);
            rs0 += __shfl_xor_sync(0xffffffffu, rs0, 2);
            rs1 += __shfl_xor_sync(0xffffffffu, rs1, 1);
            rs1 += __shfl_xor_sync(0xffffffffu, rs1, 2);
            l0 = l0 * cf0 + rs0;
            l1 = l1 * cf1 + rs1;

            #pragma unroll
            for (int nt = 0; nt < 16; ++nt) {
                o[nt][0] *= cf0; o[nt][1] *= cf0;
                o[nt][2] *= cf1; o[nt][3] *= cf1;
            }

            // ---- GEMM2: O += P @ V. A = direct repack of S C-fragments. ----
            #pragma unroll
            for (int kc2 = 0; kc2 < 4; ++kc2) {
                if (2 * kc2 <= nlim) {
                    unsigned a[4];
                    a[0] = packh2(s[2 * kc2][0],     s[2 * kc2][1]);
                    a[1] = packh2(s[2 * kc2][2],     s[2 * kc2][3]);
                    a[2] = packh2(s[2 * kc2 + 1][0], s[2 * kc2 + 1][1]);
                    a[3] = packh2(s[2 * kc2 + 1][2], s[2 * kc2 + 1][3]);

                    const float* vr = vbuf + (size_t)(kc2 * 16 + 2 * t4) * 128;
                    const int sw = t4 << 3;
                    #pragma unroll
                    for (int nt2 = 0; nt2 < 16; ++nt2) {
                        int c = (nt2 * 8 + gid) ^ sw;
                        unsigned b[2];
                        b[0] = packh2(vr[c],        vr[128 + c]);     // kv rows +0,+1
                        b[1] = packh2(vr[1024 + c], vr[1152 + c]);    // kv rows +8,+9
                        mma_f16(o[nt2], a, b);
                    }
                }
            }
        }
        __syncthreads();
    }

    // ---- epilogue: normalize and store ----
    const float inv0 = 1.f / l0;
    const float inv1 = 1.f / l1;
    float* ob0 = O + (size_t)row0 * QSTRIDE + h * HEAD_DIM + 2 * t4;
    float* ob1 = ob0 + (size_t)8 * QSTRIDE;
    #pragma unroll
    for (int nt = 0; nt < 16; ++nt) {
        float2 x0 = make_float2(o[nt][0] * inv0, o[nt][1] * inv0);
        float2 x1 = make_float2(o[nt][2] * inv1, o[nt][3] * inv1);
        *reinterpret_cast<float2*>(ob0 + nt * 8) = x0;
        *reinterpret_cast<float2*>(ob1 + nt * 8) = x1;
    }
}

extern "C" void kernel_launch(void* const* d_in, const int* in_sizes, int n_in,
                              void* d_out, int out_size)
{
    const float* Q = (const float*)d_in[0];
    const float* K = (const float*)d_in[1];
    const float* V = (const float*)d_in[2];
    float* O = (float*)d_out;

    cudaFuncSetAttribute(fa_f16_v4,
                         cudaFuncAttributeMaxDynamicSharedMemorySize, SMEM_BYTES);
    dim3 grid(2048 / BR, NUM_HEADS);
    fa_f16_v4<<<grid, NTHREADS, SMEM_BYTES>>>(Q, K, V, O);
}

// round 8
// speedup vs baseline: 2.1601x; 1.5418x over previous
#include <cuda_runtime.h>
#include <cuda_fp16.h>
#include <cstdint>

// ---------------------------------------------------------------------------
// GQA causal flash attention (prefill), fp16 mma.sync m16n8k16 + ldmatrix.
// S=2048, 32 Q heads / 8 KV heads, D=128, fp32 in/out.
// Pre-pass converts K/V to fp16 in gmem scratch; main kernel stages fp16
// tiles via cp.async double buffer and builds B fragments with ldmatrix.
// Br=128 x Bc=64, 8 warps, warp m-strip = 16 rows.
// ---------------------------------------------------------------------------

#define NUM_HEADS 32
#define HEAD_DIM  128
#define QSTRIDE   4096
#define KSTRIDE   1024
#define BR 128
#define BC 64
#define NTHREADS 256

// smem: [K0 16KB][K1 16KB][V0 16KB][V1 16KB]  (fp16 tiles, 64x128, 256B rows)
#define SMEM_BYTES (4 * 16384)

__device__ __half d_Kh[2048 * 1024];
__device__ __half d_Vh[2048 * 1024];

static __device__ __forceinline__ uint32_t smem_u32(const void* p) {
    uint32_t a;
    asm("{ .reg .u64 t; cvta.to.shared.u64 t, %1; cvt.u32.u64 %0, t; }" : "=r"(a) : "l"(p));
    return a;
}
static __device__ __forceinline__ float ex2f(float x) {
    float y; asm("ex2.approx.ftz.f32 %0, %1;" : "=f"(y) : "f"(x)); return y;
}
static __device__ __forceinline__ unsigned packh2(float lo, float hi) {
    __half2 h = __floats2half2_rn(lo, hi);
    return *reinterpret_cast<unsigned*>(&h);
}
static __device__ __forceinline__ void mma_f16(float* c, const unsigned* a,
                                               unsigned b0, unsigned b1) {
    asm("mma.sync.aligned.m16n8k16.row.col.f32.f16.f16.f32 "
        "{%0,%1,%2,%3}, {%4,%5,%6,%7}, {%8,%9}, {%0,%1,%2,%3};"
        : "+f"(c[0]), "+f"(c[1]), "+f"(c[2]), "+f"(c[3])
        : "r"(a[0]), "r"(a[1]), "r"(a[2]), "r"(a[3]), "r"(b0), "r"(b1));
}
static __device__ __forceinline__ void ldsm4(unsigned& r0, unsigned& r1,
                                             unsigned& r2, unsigned& r3, uint32_t addr) {
    asm volatile("ldmatrix.sync.aligned.m8n8.x4.shared.b16 {%0,%1,%2,%3}, [%4];"
                 : "=r"(r0), "=r"(r1), "=r"(r2), "=r"(r3) : "r"(addr));
}
static __device__ __forceinline__ void ldsm4t(unsigned& r0, unsigned& r1,
                                              unsigned& r2, unsigned& r3, uint32_t addr) {
    asm volatile("ldmatrix.sync.aligned.m8n8.x4.trans.shared.b16 {%0,%1,%2,%3}, [%4];"
                 : "=r"(r0), "=r"(r1), "=r"(r2), "=r"(r3) : "r"(addr));
}
static __device__ __forceinline__ void cpa16(uint32_t dst, const void* src) {
    asm volatile("cp.async.cg.shared.global [%0], [%1], 16;"
                 :: "r"(dst), "l"(__cvta_generic_to_global(src)) : "memory");
}
#define CP_COMMIT() asm volatile("cp.async.commit_group;" ::: "memory")
#define CP_WAIT1()  asm volatile("cp.async.wait_group 1;" ::: "memory")
#define CP_WAIT0()  asm volatile("cp.async.wait_group 0;" ::: "memory")

// ---- pre-pass: fp32 -> fp16 for K and V (1024 blocks x 256 thr x 8 elems) ----
__global__ void __launch_bounds__(256, 4)
cvt_kv(const float* __restrict__ K, const float* __restrict__ V)
{
    size_t i = ((size_t)blockIdx.x * 256 + threadIdx.x) * 8;
    float4 a = *reinterpret_cast<const float4*>(K + i);
    float4 b = *reinterpret_cast<const float4*>(K + i + 4);
    __half2 h0 = __floats2half2_rn(a.x, a.y), h1 = __floats2half2_rn(a.z, a.w);
    __half2 h2 = __floats2half2_rn(b.x, b.y), h3 = __floats2half2_rn(b.z, b.w);
    uint4 o;
    o.x = *reinterpret_cast<unsigned*>(&h0); o.y = *reinterpret_cast<unsigned*>(&h1);
    o.z = *reinterpret_cast<unsigned*>(&h2); o.w = *reinterpret_cast<unsigned*>(&h3);
    *reinterpret_cast<uint4*>(d_Kh + i) = o;
    a = *reinterpret_cast<const float4*>(V + i);
    b = *reinterpret_cast<const float4*>(V + i + 4);
    h0 = __floats2half2_rn(a.x, a.y); h1 = __floats2half2_rn(a.z, a.w);
    h2 = __floats2half2_rn(b.x, b.y); h3 = __floats2half2_rn(b.z, b.w);
    o.x = *reinterpret_cast<unsigned*>(&h0); o.y = *reinterpret_cast<unsigned*>(&h1);
    o.z = *reinterpret_cast<unsigned*>(&h2); o.w = *reinterpret_cast<unsigned*>(&h3);
    *reinterpret_cast<uint4*>(d_Vh + i) = o;
}

__global__ void __launch_bounds__(NTHREADS, 1)
fa_f16_v5(const float* __restrict__ Q, float* __restrict__ O)
{
    extern __shared__ char sm[];
    const uint32_t sb = smem_u32(sm);

    const int iq   = (int)gridDim.x - 1 - (int)blockIdx.x;   // longest first
    const int h    = blockIdx.y;
    const int g    = h >> 2;
    const int tid  = threadIdx.x;
    const int w    = tid >> 5;
    const int lane = tid & 31;
    const int gid  = lane >> 2;
    const int t4   = lane & 3;
    const int qrow0  = iq * BR;
    const int row0   = qrow0 + w * 16 + gid;
    const int row1   = row0 + 8;
    const int maxrow = qrow0 + w * 16 + 15;

    // per-lane ldmatrix address pieces
    const int rin = lane & 7;
    const int khi = (lane >> 3) & 1;     // chunk parity group
    const int qhi = (lane >> 4) & 1;     // upper half-warp group
    const uint32_t g1base = (uint32_t)((qhi * 8 + rin) * 256);   // K: n-subblock + row
    const uint32_t g2base = (uint32_t)((khi * 8 + rin) * 256);   // V: kv-subblock + row

    // ---- stage tile 0 ----
    {
        const __half* kg = d_Kh + (size_t)g * 128;
        const __half* vg = d_Vh + (size_t)g * 128;
        #pragma unroll
        for (int t = 0; t < 4; ++t) {
            int idx = tid + t * NTHREADS;
            int r = idx >> 4, c16 = idx & 15;
            uint32_t dst = (uint32_t)(r * 256 + ((c16 ^ (r & 7)) << 4));
            cpa16(sb + dst,           kg + (size_t)r * KSTRIDE + c16 * 8);
            cpa16(sb + 32768u + dst,  vg + (size_t)r * KSTRIDE + c16 * 8);
        }
        CP_COMMIT();
    }

    // ---- Q fragments (fp16, pre-scaled by softmax_scale * log2(e)) ----
    unsigned aq[8][4];
    {
        const float* q0 = Q + (size_t)row0 * QSTRIDE + h * HEAD_DIM;
        const float* q1 = q0 + (size_t)8 * QSTRIDE;
        const float sc = (float)(0.08838834764831845 * 1.4426950408889634);
        #pragma unroll
        for (int kc = 0; kc < 8; ++kc) {
            int c = kc * 16 + 2 * t4;
            aq[kc][0] = packh2(q0[c] * sc,     q0[c + 1] * sc);
            aq[kc][1] = packh2(q1[c] * sc,     q1[c + 1] * sc);
            aq[kc][2] = packh2(q0[c + 8] * sc, q0[c + 9] * sc);
            aq[kc][3] = packh2(q1[c + 8] * sc, q1[c + 9] * sc);
        }
    }

    float m0 = -1e30f, m1 = -1e30f, l0 = 0.f, l1 = 0.f;
    float o[16][4];
    #pragma unroll
    for (int nt = 0; nt < 16; ++nt)
        o[nt][0] = o[nt][1] = o[nt][2] = o[nt][3] = 0.f;

    const int jend = 2 * iq + 1;

    for (int j = 0; j <= jend; ++j) {
        if (j < jend) {
            int b = (j + 1) & 1;
            const __half* kg = d_Kh + (size_t)((j + 1) * BC) * KSTRIDE + g * 128;
            const __half* vg = d_Vh + (size_t)((j + 1) * BC) * KSTRIDE + g * 128;
            uint32_t kd = sb + (uint32_t)b * 16384u;
            uint32_t vd = sb + 32768u + (uint32_t)b * 16384u;
            #pragma unroll
            for (int t = 0; t < 4; ++t) {
                int idx = tid + t * NTHREADS;
                int r = idx >> 4, c16 = idx & 15;
                uint32_t dst = (uint32_t)(r * 256 + ((c16 ^ (r & 7)) << 4));
                cpa16(kd + dst, kg + (size_t)r * KSTRIDE + c16 * 8);
                cpa16(vd + dst, vg + (size_t)r * KSTRIDE + c16 * 8);
            }
            CP_COMMIT();
            CP_WAIT1();
        } else {
            CP_WAIT0();
        }
        __syncthreads();

        const uint32_t kb = sb + (uint32_t)(j & 1) * 16384u;
        const uint32_t vb = sb + 32768u + (uint32_t)(j & 1) * 16384u;

        const int d = maxrow - BC * j;
        if (d >= 0) {
            // ---- GEMM1: S = Q @ K^T (B via ldmatrix non-trans) ----
            float s[8][4];
            #pragma unroll
            for (int nt = 0; nt < 8; ++nt)
                s[nt][0] = s[nt][1] = s[nt][2] = s[nt][3] = 0.f;

            #pragma unroll
            for (int kc = 0; kc < 8; ++kc) {
                const int kch = kc * 2 + khi;
                #pragma unroll
                for (int ntp = 0; ntp < 4; ++ntp) {
                    if (16 * ntp <= d) {
                        unsigned b0, b1, b2, b3;
                        ldsm4(b0, b1, b2, b3,
                              kb + g1base + (uint32_t)(ntp * 4096) +
                              (uint32_t)(((kch ^ rin) & 15) << 4));
                        mma_f16(s[2 * ntp],     aq[kc], b0, b1);
                        mma_f16(s[2 * ntp + 1], aq[kc], b2, b3);
                    }
                }
            }

            // ---- mask + online softmax (log2 domain) ----
            const bool diag = (j >= 2 * iq);
            float mx0 = -1e30f, mx1 = -1e30f;
            #pragma unroll
            for (int nt = 0; nt < 8; ++nt) {
                if (diag) {
                    int col = j * BC + nt * 8 + 2 * t4;
                    if (col     > row0) s[nt][0] = -1e30f;
                    if (col + 1 > row0) s[nt][1] = -1e30f;
                    if (col     > row1) s[nt][2] = -1e30f;
                    if (col + 1 > row1) s[nt][3] = -1e30f;
                }
                mx0 = fmaxf(mx0, fmaxf(s[nt][0], s[nt][1]));
                mx1 = fmaxf(mx1, fmaxf(s[nt][2], s[nt][3]));
            }
            mx0 = fmaxf(mx0, __shfl_xor_sync(0xffffffffu, mx0, 1));
            mx0 = fmaxf(mx0, __shfl_xor_sync(0xffffffffu, mx0, 2));
            mx1 = fmaxf(mx1, __shfl_xor_sync(0xffffffffu, mx1, 1));
            mx1 = fmaxf(mx1, __shfl_xor_sync(0xffffffffu, mx1, 2));

            const float nm0 = fmaxf(m0, mx0);
            const float nm1 = fmaxf(m1, mx1);
            const float cf0 = ex2f(m0 - nm0);
            const float cf1 = ex2f(m1 - nm1);
            m0 = nm0; m1 = nm1;

            float rs0 = 0.f, rs1 = 0.f;
            #pragma unroll
            for (int nt = 0; nt < 8; ++nt) {
                float p0 = ex2f(s[nt][0] - m0);
                float p1 = ex2f(s[nt][1] - m0);
                float p2 = ex2f(s[nt][2] - m1);
                float p3 = ex2f(s[nt][3] - m1);
                rs0 += p0 + p1; rs1 += p2 + p3;
                s[nt][0] = p0; s[nt][1] = p1; s[nt][2] = p2; s[nt][3] = p3;
            }
            rs0 += __shfl_xor_sync(0xffffffffu, rs0, 1);
            rs0 += __shfl_xor_sync(0xffffffffu, rs0, 2);
            rs1 += __shfl_xor_sync(0xffffffffu, rs1, 1);
            rs1 += __shfl_xor_sync(0xffffffffu, rs1, 2);
            l0 = l0 * cf0 + rs0;
            l1 = l1 * cf1 + rs1;

            #pragma unroll
            for (int nt = 0; nt < 16; ++nt) {
                o[nt][0] *= cf0; o[nt][1] *= cf0;
                o[nt][2] *= cf1; o[nt][3] *= cf1;
            }

            // ---- GEMM2: O += P @ V (A = repacked S frags, B via ldmatrix.trans) ----
            #pragma unroll
            for (int kc2 = 0; kc2 < 4; ++kc2) {
                if (16 * kc2 <= d) {
                    unsigned a[4];
                    a[0] = packh2(s[2 * kc2][0],     s[2 * kc2][1]);
                    a[1] = packh2(s[2 * kc2][2],     s[2 * kc2][3]);
                    a[2] = packh2(s[2 * kc2 + 1][0], s[2 * kc2 + 1][1]);
                    a[3] = packh2(s[2 * kc2 + 1][2], s[2 * kc2 + 1][3]);
                    #pragma unroll
                    for (int ntp2 = 0; ntp2 < 8; ++ntp2) {
                        unsigned b0, b1, b2, b3;
                        ldsm4t(b0, b1, b2, b3,
                               vb + g2base + (uint32_t)(kc2 * 4096) +
                               (uint32_t)((((2 * ntp2 + qhi) ^ rin) & 15) << 4));
                        mma_f16(o[2 * ntp2],     a, b0, b1);
                        mma_f16(o[2 * ntp2 + 1], a, b2, b3);
                    }
                }
            }
        }
        __syncthreads();
    }

    // ---- epilogue: normalize and store ----
    const float inv0 = 1.f / l0;
    const float inv1 = 1.f / l1;
    float* ob0 = O + (size_t)row0 * QSTRIDE + h * HEAD_DIM + 2 * t4;
    float* ob1 = ob0 + (size_t)8 * QSTRIDE;
    #pragma unroll
    for (int nt = 0; nt < 16; ++nt) {
        float2 x0 = make_float2(o[nt][0] * inv0, o[nt][1] * inv0);
        float2 x1 = make_float2(o[nt][2] * inv1, o[nt][3] * inv1);
        *reinterpret_cast<float2*>(ob0 + nt * 8) = x0;
        *reinterpret_cast<float2*>(ob1 + nt * 8) = x1;
    }
}

extern "C" void kernel_launch(void* const* d_in, const int* in_sizes, int n_in,
                              void* d_out, int out_size)
{
    const float* Q = (const float*)d_in[0];
    const float* K = (const float*)d_in[1];
    const float* V = (const float*)d_in[2];
    float* O = (float*)d_out;

    cvt_kv<<<1024, 256>>>(K, V);

    cudaFuncSetAttribute(fa_f16_v5,
                         cudaFuncAttributeMaxDynamicSharedMemorySize, SMEM_BYTES);
    dim3 grid(2048 / BR, NUM_HEADS);
    fa_f16_v5<<<grid, NTHREADS, SMEM_BYTES>>>(Q, O);
}